// round 1
// baseline (speedup 1.0000x reference)
#include <cuda_runtime.h>
#include <math.h>

#define NROWS 100000
#define MTRIP 800000
#define HID   128
#define HEADS 8

// ---------------- scratch (static device globals; no allocs allowed) ----------------
__device__ float g_q[NROWS * HID];
__device__ float g_k[NROWS * HID];
__device__ float g_v[NROWS * HID];
__device__ float g_agg[NROWS * HID];
__device__ float g_h1[NROWS * HID];
__device__ float g_att[MTRIP * HEADS];
__device__ float g_denom[NROWS * HEADS];
__device__ int   g_is64;

// ---------------- index dtype detection (jax may canonicalize int64 -> int32) -------
__global__ void detect_kernel(const unsigned int* raw, int m) {
    __shared__ int nz;
    if (threadIdx.x == 0) nz = 0;
    __syncthreads();
    int c = m < 2048 ? m : 2048;
    int local = 0;
    for (int i = threadIdx.x; i < c; i += blockDim.x) {
        // If data is int64 little-endian with values < 2^31, all odd words are 0.
        if (raw[2 * i + 1] != 0u) local = 1;
    }
    if (local) atomicOr(&nz, 1);
    __syncthreads();
    if (threadIdx.x == 0) g_is64 = (nz == 0) ? 1 : 0;
}

__device__ __forceinline__ long long load_idx(const void* p, int i, bool is64) {
    return is64 ? ((const long long*)p)[i] : (long long)((const int*)p)[i];
}

// ---------------- zero init for denom + agg ----------------------------------------
__global__ void zero_kernel() {
    const int d4 = (NROWS * HEADS) / 4;      // 200000
    const int a4 = (NROWS * HID) / 4;        // 3200000
    const int total = d4 + a4;
    float4 z = make_float4(0.f, 0.f, 0.f, 0.f);
    for (int i = blockIdx.x * blockDim.x + threadIdx.x; i < total;
         i += gridDim.x * blockDim.x) {
        if (i < d4) ((float4*)g_denom)[i] = z;
        else        ((float4*)g_agg)[i - d4] = z;
    }
}

// ---------------- fp32 GEMM: out[r][o] = sum_i A[r][i] * W[o][i]  (+bias,+relu,+add) -
// Block tile: 64 rows x 128 cols, K=128 fully in shared. 128 threads,
// per-thread tile 8 rows x 8 cols with f32x2 packed FFMA (FFMA2).
#define GEMM_SMEM ((128 * 129 + 64 * 129) * 4)

__global__ __launch_bounds__(128, 2)
void gemm_kernel(const float* __restrict__ A, const float* __restrict__ W,
                 const float* __restrict__ bias, const float* __restrict__ addsrc,
                 float* __restrict__ out, int nrows, int dorelu) {
    extern __shared__ float smem[];
    float* Ws = smem;               // [128][129]
    float* As = smem + 128 * 129;   // [64][129]

    const int tid = threadIdx.x;          // 128 threads
    const int tx = tid & 15;               // col group
    const int ty = tid >> 4;               // row group (0..7)
    const int row0 = blockIdx.x * 64;

    // Stage W (128x128) coalesced float4 reads, padded scalar stores
#pragma unroll
    for (int it = 0; it < 32; ++it) {
        int e4 = tid + it * 128;
        int o = e4 >> 5, i0 = (e4 & 31) << 2;
        float4 w = ((const float4*)W)[e4];
        float* dst = &Ws[o * 129 + i0];
        dst[0] = w.x; dst[1] = w.y; dst[2] = w.z; dst[3] = w.w;
    }
    // Stage A (64x128) with row guard
#pragma unroll
    for (int it = 0; it < 16; ++it) {
        int e4 = tid + it * 128;
        int r = e4 >> 5, i0 = (e4 & 31) << 2;
        float4 a;
        if (row0 + r < nrows)
            a = ((const float4*)(A + (size_t)(row0 + r) * HID))[e4 & 31];
        else
            a = make_float4(0.f, 0.f, 0.f, 0.f);
        float* dst = &As[r * 129 + i0];
        dst[0] = a.x; dst[1] = a.y; dst[2] = a.z; dst[3] = a.w;
    }
    __syncthreads();

    // Accumulators: acc[jr][jc] = {col tx+32*jc, col tx+32*jc+16} for row ty+8*jr
    unsigned long long acc[8][4];
#pragma unroll
    for (int i = 0; i < 8; ++i)
#pragma unroll
        for (int j = 0; j < 4; ++j) acc[i][j] = 0ull;

#pragma unroll 4
    for (int kk = 0; kk < 128; ++kk) {
        float a[8], b[8];
#pragma unroll
        for (int j = 0; j < 8; ++j) a[j] = As[(ty + 8 * j) * 129 + kk];
#pragma unroll
        for (int j = 0; j < 8; ++j) b[j] = Ws[(tx + 16 * j) * 129 + kk];
        unsigned long long ad[8], bd[4];
#pragma unroll
        for (int j = 0; j < 8; ++j)
            asm("mov.b64 %0, {%1, %1};" : "=l"(ad[j]) : "f"(a[j]));
#pragma unroll
        for (int j = 0; j < 4; ++j)
            asm("mov.b64 %0, {%1, %2};" : "=l"(bd[j]) : "f"(b[2 * j]), "f"(b[2 * j + 1]));
#pragma unroll
        for (int jr = 0; jr < 8; ++jr)
#pragma unroll
            for (int jc = 0; jc < 4; ++jc)
                asm("fma.rn.f32x2 %0, %1, %2, %0;"
                    : "+l"(acc[jr][jc]) : "l"(ad[jr]), "l"(bd[jc]));
    }

    // Epilogue
#pragma unroll
    for (int jr = 0; jr < 8; ++jr) {
        int r = row0 + ty + 8 * jr;
        if (r >= nrows) continue;
#pragma unroll
        for (int jc = 0; jc < 4; ++jc) {
            float x, y;
            asm("mov.b64 {%0, %1}, %2;" : "=f"(x), "=f"(y) : "l"(acc[jr][jc]));
            int c0 = tx + 32 * jc, c1 = c0 + 16;
            if (bias) { x += bias[c0]; y += bias[c1]; }
            if (dorelu) { x = fmaxf(x, 0.f); y = fmaxf(y, 0.f); }
            if (addsrc) {
                x += addsrc[(size_t)r * HID + c0];
                y += addsrc[(size_t)r * HID + c1];
            }
            out[(size_t)r * HID + c0] = x;
            out[(size_t)r * HID + c1] = y;
        }
    }
}

// ---------------- attention scores + denom ------------------------------------------
// One warp per triplet. DH=16 -> 4 lanes per head with float4 loads.
__global__ void att_kernel(const void* __restrict__ idx_kj,
                           const void* __restrict__ idx_ji, int m_total) {
    int w = (blockIdx.x * blockDim.x + threadIdx.x) >> 5;
    int lane = threadIdx.x & 31;
    if (w >= m_total) return;
    bool is64 = (g_is64 != 0);
    long long kj = load_idx(idx_kj, w, is64);
    long long ji = load_idx(idx_ji, w, is64);

    float4 qv = ((const float4*)g_q)[kj * 32 + lane];
    float4 kv = ((const float4*)g_k)[ji * 32 + lane];
    float d = qv.x * kv.x + qv.y * kv.y + qv.z * kv.z + qv.w * kv.w;
    d += __shfl_xor_sync(0xffffffffu, d, 1);
    d += __shfl_xor_sync(0xffffffffu, d, 2);

    if ((lane & 3) == 0) {
        int h = lane >> 2;
        float s = d > 0.f ? d : 0.2f * d;   // leaky_relu(0.2)
        float a = expf(s);
        g_att[(size_t)w * HEADS + h] = a;
        atomicAdd(&g_denom[ji * HEADS + h], a);
    }
}

// ---------------- weighted V scatter -------------------------------------------------
__global__ void agg_kernel(const void* __restrict__ idx_kj,
                           const void* __restrict__ idx_ji, int m_total) {
    int w = (blockIdx.x * blockDim.x + threadIdx.x) >> 5;
    int lane = threadIdx.x & 31;
    if (w >= m_total) return;
    bool is64 = (g_is64 != 0);
    long long kj = load_idx(idx_kj, w, is64);
    long long ji = load_idx(idx_ji, w, is64);

    int h = lane >> 2;
    float a = g_att[(size_t)w * HEADS + h];
    float den = g_denom[ji * HEADS + h];
    float s = a / den;

    float4 vv = ((const float4*)g_v)[kj * 32 + lane];
    float x = vv.x * s, y = vv.y * s, z = vv.z * s, u = vv.w * s;
    float* dst = &g_agg[ji * HID + lane * 4];
    asm volatile("red.global.add.v4.f32 [%0], {%1, %2, %3, %4};"
                 :: "l"(dst), "f"(x), "f"(y), "f"(z), "f"(u) : "memory");
}

// ---------------- launch ----------------------------------------------------------
extern "C" void kernel_launch(void* const* d_in, const int* in_sizes, int n_in,
                              void* d_out, int out_size) {
    const float* feats = (const float*)d_in[0];
    const void*  idx_kj = d_in[1];
    const void*  idx_ji = d_in[2];
    const float* Wv = (const float*)d_in[3];
    const float* Wq = (const float*)d_in[4];
    const float* Wk = (const float*)d_in[5];
    const float* W1 = (const float*)d_in[6];
    const float* b1 = (const float*)d_in[7];
    const float* W2 = (const float*)d_in[8];
    const float* b2 = (const float*)d_in[9];
    float* out = (float*)d_out;

    int nrows = in_sizes[0] / HID;   // N
    int m     = in_sizes[1];         // M (element count regardless of int32/int64)

    float *q_p, *k_p, *v_p, *agg_p, *h1_p;
    cudaGetSymbolAddress((void**)&q_p,   g_q);
    cudaGetSymbolAddress((void**)&k_p,   g_k);
    cudaGetSymbolAddress((void**)&v_p,   g_v);
    cudaGetSymbolAddress((void**)&agg_p, g_agg);
    cudaGetSymbolAddress((void**)&h1_p,  g_h1);

    cudaFuncSetAttribute(gemm_kernel, cudaFuncAttributeMaxDynamicSharedMemorySize,
                         GEMM_SMEM);

    detect_kernel<<<1, 256>>>((const unsigned int*)idx_kj, m);
    zero_kernel<<<2048, 256>>>();

    int gblocks = (nrows + 63) / 64;
    gemm_kernel<<<gblocks, 128, GEMM_SMEM>>>(feats, Wq, nullptr, nullptr, q_p, nrows, 0);
    gemm_kernel<<<gblocks, 128, GEMM_SMEM>>>(feats, Wk, nullptr, nullptr, k_p, nrows, 0);
    gemm_kernel<<<gblocks, 128, GEMM_SMEM>>>(feats, Wv, nullptr, nullptr, v_p, nrows, 0);

    int ablocks = (m + 7) / 8;   // one warp per triplet, 256-thread blocks
    att_kernel<<<ablocks, 256>>>(idx_kj, idx_ji, m);
    agg_kernel<<<ablocks, 256>>>(idx_kj, idx_ji, m);

    gemm_kernel<<<gblocks, 128, GEMM_SMEM>>>(agg_p, W1, b1, nullptr, h1_p, nrows, 1);
    gemm_kernel<<<gblocks, 128, GEMM_SMEM>>>(h1_p, W2, b2, v_p, out, nrows, 1);
}

// round 3
// speedup vs baseline: 1.1428x; 1.1428x over previous
#include <cuda_runtime.h>
#include <math.h>
#include <stdint.h>

#define NROWS 100000
#define MTRIP 800000
#define HID   128
#define HEADS 8

// ---------------- scratch (static device globals; no allocs allowed) ----------------
__device__ float g_q[NROWS * HID];
__device__ float g_k[NROWS * HID];
__device__ float g_v[NROWS * HID];
__device__ float g_agg[NROWS * HID];
__device__ float g_h1[NROWS * HID];
__device__ float g_att[MTRIP * HEADS];
__device__ float g_denom[NROWS * HEADS];
__device__ int   g_is64;

// ---------------- index dtype detection ----------------
__global__ void detect_kernel(const unsigned int* raw, int m) {
    __shared__ int nz;
    if (threadIdx.x == 0) nz = 0;
    __syncthreads();
    int c = m < 2048 ? m : 2048;
    int local = 0;
    for (int i = threadIdx.x; i < c; i += blockDim.x)
        if (raw[2 * i + 1] != 0u) local = 1;
    if (local) atomicOr(&nz, 1);
    __syncthreads();
    if (threadIdx.x == 0) g_is64 = (nz == 0) ? 1 : 0;
}

__device__ __forceinline__ long long load_idx(const void* p, int i, bool is64) {
    return is64 ? ((const long long*)p)[i] : (long long)((const int*)p)[i];
}

// ---------------- zero init ----------------
__global__ void zero_kernel() {
    const int d4 = (NROWS * HEADS) / 4;
    const int a4 = (NROWS * HID) / 4;
    const int total = d4 + a4;
    float4 z = make_float4(0.f, 0.f, 0.f, 0.f);
    for (int i = blockIdx.x * blockDim.x + threadIdx.x; i < total;
         i += gridDim.x * blockDim.x) {
        if (i < d4) ((float4*)g_denom)[i] = z;
        else        ((float4*)g_agg)[i - d4] = z;
    }
}

// ================== tf32x3 GEMM via mma.sync (sm_80+ path; no arch-'a' PTX) ==========
// out[r][o] = sum_i A[r][i] * W[o][i]  (+bias, +relu, +addsrc)
// CTA: 256 threads (8 warps), tile 128 rows x 128 cols, K=128 staged in SMEM.
// Warp tile 32x64 via m16n8k8 tf32 fragments; 3-term hi/lo split for fp32 accuracy.

#define APAD 132   // 132 mod 32 = 4 -> A frag loads (4g+tg) conflict-free
#define GEMM_SMEM ((128 * APAD * 2) * 4)

__device__ __forceinline__ uint32_t f2tf32(float f) {
    uint32_t u;
    asm("cvt.rna.tf32.f32 %0, %1;" : "=r"(u) : "f"(f));
    return u;
}
__device__ __forceinline__ void split32(float a, uint32_t& hi, uint32_t& lo) {
    hi = f2tf32(a);
    lo = f2tf32(a - __uint_as_float(hi));
}
__device__ __forceinline__ void mma8(float c[4], const uint32_t a[4], const uint32_t b[2]) {
    asm volatile(
        "mma.sync.aligned.m16n8k8.row.col.f32.tf32.tf32.f32 "
        "{%0,%1,%2,%3}, {%4,%5,%6,%7}, {%8,%9}, {%0,%1,%2,%3};"
        : "+f"(c[0]), "+f"(c[1]), "+f"(c[2]), "+f"(c[3])
        : "r"(a[0]), "r"(a[1]), "r"(a[2]), "r"(a[3]), "r"(b[0]), "r"(b[1]));
}

__global__ __launch_bounds__(256, 1)
void gemm_mma(const float* __restrict__ A, const float* __restrict__ W,
              const float* __restrict__ bias, const float* __restrict__ addsrc,
              float* __restrict__ out, int nrows, int dorelu) {
    extern __shared__ float smem[];
    float* As = smem;               // [128][APAD]
    float* Ws = smem + 128 * APAD;  // [128][APAD]  (W row-major: Ws[o][i])

    const int tid = threadIdx.x;
    const int lane = tid & 31;
    const int wid = tid >> 5;          // 0..7
    const int wm = wid & 3;            // row block: 32 rows
    const int wn = wid >> 2;           // col block: 64 cols
    const int g  = lane >> 2;          // groupID 0..7
    const int tg = lane & 3;           // thread-in-group 0..3
    const int row0 = blockIdx.x * 128;

    // ---- stage W (128x128) and A (128x128) coalesced, float4 ----
#pragma unroll
    for (int it = 0; it < 16; ++it) {
        int e4 = tid + it * 256;
        int r = e4 >> 5, k4 = e4 & 31;
        float4 w = ((const float4*)W)[e4];
        *(float4*)&Ws[r * APAD + 4 * k4] = w;
        float4 a;
        if (row0 + r < nrows)
            a = ((const float4*)(A + (size_t)(row0 + r) * HID))[k4];
        else
            a = make_float4(0.f, 0.f, 0.f, 0.f);
        *(float4*)&As[r * APAD + 4 * k4] = a;
    }
    __syncthreads();

    // ---- accumulators: [mf=2][nf=8][4] ----
    float acc[2][8][4];
#pragma unroll
    for (int i = 0; i < 2; ++i)
#pragma unroll
        for (int j = 0; j < 8; ++j)
#pragma unroll
            for (int q = 0; q < 4; ++q) acc[i][j][q] = 0.f;

#pragma unroll 1
    for (int ks = 0; ks < 16; ++ks) {
        const int k0 = ks * 8;
        // A fragments (m16k8) hi/lo for mf=0,1
        uint32_t ahi[2][4], alo[2][4];
#pragma unroll
        for (int mf = 0; mf < 2; ++mf) {
            int br = wm * 32 + mf * 16;
            float a0 = As[(br + g) * APAD + k0 + tg];
            float a1 = As[(br + g + 8) * APAD + k0 + tg];
            float a2 = As[(br + g) * APAD + k0 + tg + 4];
            float a3 = As[(br + g + 8) * APAD + k0 + tg + 4];
            split32(a0, ahi[mf][0], alo[mf][0]);
            split32(a1, ahi[mf][1], alo[mf][1]);
            split32(a2, ahi[mf][2], alo[mf][2]);
            split32(a3, ahi[mf][3], alo[mf][3]);
        }
        // B fragments (k8n8, col) hi/lo for nf=0..7; B[k][n] = W[n][k] = Ws[n][k]
        uint32_t bhi[8][2], blo[8][2];
#pragma unroll
        for (int nf = 0; nf < 8; ++nf) {
            int col = wn * 64 + nf * 8 + g;
            float b0 = Ws[col * APAD + k0 + tg];
            float b1 = Ws[col * APAD + k0 + tg + 4];
            split32(b0, bhi[nf][0], blo[nf][0]);
            split32(b1, bhi[nf][1], blo[nf][1]);
        }
        // 3-term MMA
#pragma unroll
        for (int mf = 0; mf < 2; ++mf)
#pragma unroll
            for (int nf = 0; nf < 8; ++nf) {
                mma8(acc[mf][nf], ahi[mf], bhi[nf]);
                mma8(acc[mf][nf], ahi[mf], blo[nf]);
                mma8(acc[mf][nf], alo[mf], bhi[nf]);
            }
    }

    // ---- epilogue: direct float2 stores ----
#pragma unroll
    for (int mf = 0; mf < 2; ++mf) {
#pragma unroll
        for (int half = 0; half < 2; ++half) {
            int r = row0 + wm * 32 + mf * 16 + g + half * 8;
            if (r >= nrows) continue;
#pragma unroll
            for (int nf = 0; nf < 8; ++nf) {
                int col = wn * 64 + nf * 8 + 2 * tg;
                float x = acc[mf][nf][half * 2 + 0];
                float y = acc[mf][nf][half * 2 + 1];
                if (bias) { x += bias[col]; y += bias[col + 1]; }
                if (dorelu) { x = fmaxf(x, 0.f); y = fmaxf(y, 0.f); }
                if (addsrc) {
                    const float* ap = addsrc + (size_t)r * HID + col;
                    x += ap[0]; y += ap[1];
                }
                float2 o2 = make_float2(x, y);
                *(float2*)(out + (size_t)r * HID + col) = o2;
            }
        }
    }
}

// ---------------- attention scores + denom ----------------
__global__ void att_kernel(const void* __restrict__ idx_kj,
                           const void* __restrict__ idx_ji, int m_total) {
    int w = (blockIdx.x * blockDim.x + threadIdx.x) >> 5;
    int lane = threadIdx.x & 31;
    if (w >= m_total) return;
    bool is64 = (g_is64 != 0);
    long long kj = load_idx(idx_kj, w, is64);
    long long ji = load_idx(idx_ji, w, is64);

    float4 qv = ((const float4*)g_q)[kj * 32 + lane];
    float4 kv = ((const float4*)g_k)[ji * 32 + lane];
    float d = qv.x * kv.x + qv.y * kv.y + qv.z * kv.z + qv.w * kv.w;
    d += __shfl_xor_sync(0xffffffffu, d, 1);
    d += __shfl_xor_sync(0xffffffffu, d, 2);

    if ((lane & 3) == 0) {
        int h = lane >> 2;
        float s = d > 0.f ? d : 0.2f * d;   // leaky_relu(0.2)
        float a = expf(s);
        g_att[(size_t)w * HEADS + h] = a;
        atomicAdd(&g_denom[ji * HEADS + h], a);
    }
}

// ---------------- weighted V scatter ----------------
__global__ void agg_kernel(const void* __restrict__ idx_kj,
                           const void* __restrict__ idx_ji, int m_total) {
    int w = (blockIdx.x * blockDim.x + threadIdx.x) >> 5;
    int lane = threadIdx.x & 31;
    if (w >= m_total) return;
    bool is64 = (g_is64 != 0);
    long long kj = load_idx(idx_kj, w, is64);
    long long ji = load_idx(idx_ji, w, is64);

    int h = lane >> 2;
    float a = g_att[(size_t)w * HEADS + h];
    float den = g_denom[ji * HEADS + h];
    float s = a / den;

    float4 vv = ((const float4*)g_v)[kj * 32 + lane];
    float x = vv.x * s, y = vv.y * s, z = vv.z * s, u = vv.w * s;
    float* dst = &g_agg[ji * HID + lane * 4];
    asm volatile("red.global.add.v4.f32 [%0], {%1, %2, %3, %4};"
                 :: "l"(dst), "f"(x), "f"(y), "f"(z), "f"(u) : "memory");
}

// ---------------- launch ----------------
extern "C" void kernel_launch(void* const* d_in, const int* in_sizes, int n_in,
                              void* d_out, int out_size) {
    const float* feats = (const float*)d_in[0];
    const void*  idx_kj = d_in[1];
    const void*  idx_ji = d_in[2];
    const float* Wv = (const float*)d_in[3];
    const float* Wq = (const float*)d_in[4];
    const float* Wk = (const float*)d_in[5];
    const float* W1 = (const float*)d_in[6];
    const float* b1 = (const float*)d_in[7];
    const float* W2 = (const float*)d_in[8];
    const float* b2 = (const float*)d_in[9];
    float* out = (float*)d_out;

    int nrows = in_sizes[0] / HID;
    int m     = in_sizes[1];

    float *q_p, *k_p, *v_p, *agg_p, *h1_p;
    cudaGetSymbolAddress((void**)&q_p,   g_q);
    cudaGetSymbolAddress((void**)&k_p,   g_k);
    cudaGetSymbolAddress((void**)&v_p,   g_v);
    cudaGetSymbolAddress((void**)&agg_p, g_agg);
    cudaGetSymbolAddress((void**)&h1_p,  g_h1);

    cudaFuncSetAttribute(gemm_mma, cudaFuncAttributeMaxDynamicSharedMemorySize,
                         GEMM_SMEM);

    detect_kernel<<<1, 256>>>((const unsigned int*)idx_kj, m);
    zero_kernel<<<2048, 256>>>();

    int gblocks = (nrows + 127) / 128;
    gemm_mma<<<gblocks, 256, GEMM_SMEM>>>(feats, Wq, nullptr, nullptr, q_p, nrows, 0);
    gemm_mma<<<gblocks, 256, GEMM_SMEM>>>(feats, Wk, nullptr, nullptr, k_p, nrows, 0);
    gemm_mma<<<gblocks, 256, GEMM_SMEM>>>(feats, Wv, nullptr, nullptr, v_p, nrows, 0);

    int ablocks = (m + 7) / 8;
    att_kernel<<<ablocks, 256>>>(idx_kj, idx_ji, m);
    agg_kernel<<<ablocks, 256>>>(idx_kj, idx_ji, m);

    gemm_mma<<<gblocks, 256, GEMM_SMEM>>>(agg_p, W1, b1, nullptr, h1_p, nrows, 1);
    gemm_mma<<<gblocks, 256, GEMM_SMEM>>>(h1_p, W2, b2, v_p, out, nrows, 1);
}

// round 4
// speedup vs baseline: 1.2869x; 1.1262x over previous
#include <cuda_runtime.h>
#include <math.h>
#include <stdint.h>

#define NROWS 100000
#define MTRIP 800000
#define HID   128
#define HEADS 8
#define APAD  132
#define NBLK  ((NROWS + 1023) / 1024)
#define GEMM_SMEM ((128 * APAD * 2) * 4)

// ---------------- scratch (static device globals; no allocs allowed) ----------------
__device__ float g_q[NROWS * HID];
__device__ float g_k[NROWS * HID];
__device__ float g_v[NROWS * HID];
__device__ float g_agg[NROWS * HID];
__device__ float g_h1[NROWS * HID];
__device__ int   g_hist[NROWS + 1];   // exclusive segment offsets after scan
__device__ int   g_cursor[NROWS];
__device__ int   g_bsums[NBLK];
__device__ int   g_perm[MTRIP];
__device__ int   g_is64;

// ---------------- index dtype detection ----------------
__global__ void detect_kernel(const unsigned int* raw, int m) {
    __shared__ int nz;
    if (threadIdx.x == 0) nz = 0;
    __syncthreads();
    int c = m < 2048 ? m : 2048;
    int local = 0;
    for (int i = threadIdx.x; i < c; i += blockDim.x)
        if (raw[2 * i + 1] != 0u) local = 1;
    if (local) atomicOr(&nz, 1);
    __syncthreads();
    if (threadIdx.x == 0) g_is64 = (nz == 0) ? 1 : 0;
}

__device__ __forceinline__ long long load_idx(const void* p, int i, bool is64) {
    return is64 ? ((const long long*)p)[i] : (long long)((const int*)p)[i];
}

// ---------------- counting sort by destination (idx_ji) ----------------
__global__ void zero_hist() {
    for (int i = blockIdx.x * blockDim.x + threadIdx.x; i <= NROWS;
         i += gridDim.x * blockDim.x)
        g_hist[i] = 0;
}

__global__ void hist_kernel(const void* __restrict__ idx_ji, int m) {
    bool is64 = (g_is64 != 0);
    for (int e = blockIdx.x * blockDim.x + threadIdx.x; e < m;
         e += gridDim.x * blockDim.x)
        atomicAdd(&g_hist[(int)load_idx(idx_ji, e, is64)], 1);
}

__global__ void scan1_kernel() {
    __shared__ int s[1024];
    int t = threadIdx.x;
    int i = blockIdx.x * 1024 + t;
    int v = (i < NROWS) ? g_hist[i] : 0;
    s[t] = v;
    __syncthreads();
#pragma unroll
    for (int off = 1; off < 1024; off <<= 1) {
        int x = (t >= off) ? s[t - off] : 0;
        __syncthreads();
        s[t] += x;
        __syncthreads();
    }
    if (i < NROWS) g_hist[i] = s[t] - v;   // exclusive within block
    if (t == 1023) g_bsums[blockIdx.x] = s[t];
}

__global__ void scan2_kernel() {
    int running = 0;
    for (int b = 0; b < NBLK; ++b) {
        int t = g_bsums[b];
        g_bsums[b] = running;
        running += t;
    }
    g_hist[NROWS] = running;   // = M
}

__global__ void scan3_kernel() {
    for (int i = blockIdx.x * blockDim.x + threadIdx.x; i < NROWS;
         i += gridDim.x * blockDim.x) {
        int v = g_hist[i] + g_bsums[i >> 10];
        g_hist[i] = v;
        g_cursor[i] = v;
    }
}

__global__ void scatter_kernel(const void* __restrict__ idx_ji, int m) {
    bool is64 = (g_is64 != 0);
    for (int e = blockIdx.x * blockDim.x + threadIdx.x; e < m;
         e += gridDim.x * blockDim.x) {
        int d = (int)load_idx(idx_ji, e, is64);
        int pos = atomicAdd(&g_cursor[d], 1);
        g_perm[pos] = e;
    }
}

// ================== tf32x3 GEMM core via mma.sync, software-pipelined ==============
__device__ __forceinline__ uint32_t f2tf32(float f) {
    uint32_t u;
    asm("cvt.rna.tf32.f32 %0, %1;" : "=r"(u) : "f"(f));
    return u;
}
__device__ __forceinline__ void split32(float a, uint32_t& hi, uint32_t& lo) {
    hi = f2tf32(a);
    lo = f2tf32(a - __uint_as_float(hi));
}
__device__ __forceinline__ void mma8(float c[4], const uint32_t a[4], const uint32_t b[2]) {
    asm volatile(
        "mma.sync.aligned.m16n8k8.row.col.f32.tf32.tf32.f32 "
        "{%0,%1,%2,%3}, {%4,%5,%6,%7}, {%8,%9}, {%0,%1,%2,%3};"
        : "+f"(c[0]), "+f"(c[1]), "+f"(c[2]), "+f"(c[3])
        : "r"(a[0]), "r"(a[1]), "r"(a[2]), "r"(a[3]), "r"(b[0]), "r"(b[1]));
}

#define LOAD_FRAGS(fa, fb, k0)                                            \
    {                                                                     \
        _Pragma("unroll") for (int mf = 0; mf < 2; ++mf) {                \
            int br = wm * 32 + mf * 16;                                   \
            fa[mf][0] = As[(br + g) * APAD + (k0) + tg];                  \
            fa[mf][1] = As[(br + g + 8) * APAD + (k0) + tg];              \
            fa[mf][2] = As[(br + g) * APAD + (k0) + tg + 4];              \
            fa[mf][3] = As[(br + g + 8) * APAD + (k0) + tg + 4];          \
        }                                                                 \
        _Pragma("unroll") for (int nf = 0; nf < 8; ++nf) {                \
            int col = wn * 64 + nf * 8 + g;                               \
            fb[nf][0] = Ws[col * APAD + (k0) + tg];                       \
            fb[nf][1] = Ws[col * APAD + (k0) + tg + 4];                   \
        }                                                                 \
    }

__device__ __noinline__ void gemm_core(float* As, float* Ws,
                                       const float* __restrict__ W,
                                       const float* __restrict__ bias,
                                       const float* __restrict__ addsrc,
                                       float* __restrict__ out,
                                       int nrows, int row0, int dorelu) {
    const int tid = threadIdx.x;
    const int lane = tid & 31;
    const int wid = tid >> 5;
    const int wm = wid & 3, wn = wid >> 2;
    const int g = lane >> 2, tg = lane & 3;

    __syncthreads();   // previous consumers of Ws done
#pragma unroll
    for (int it = 0; it < 16; ++it) {
        int e4 = tid + it * 256;
        int r = e4 >> 5, k4 = e4 & 31;
        *(float4*)&Ws[r * APAD + 4 * k4] = ((const float4*)W)[e4];
    }
    __syncthreads();

    float acc[2][8][4];
#pragma unroll
    for (int i = 0; i < 2; ++i)
#pragma unroll
        for (int j = 0; j < 8; ++j)
#pragma unroll
            for (int q = 0; q < 4; ++q) acc[i][j][q] = 0.f;

    float cura[2][4], curb[8][2], nxta[2][4], nxtb[8][2];
    LOAD_FRAGS(cura, curb, 0)

#pragma unroll 4
    for (int ks = 0; ks < 16; ++ks) {
        if (ks < 15) LOAD_FRAGS(nxta, nxtb, (ks + 1) * 8)

        uint32_t ahi[2][4], alo[2][4], bhi[8][2], blo[8][2];
#pragma unroll
        for (int mf = 0; mf < 2; ++mf)
#pragma unroll
            for (int q = 0; q < 4; ++q)
                split32(cura[mf][q], ahi[mf][q], alo[mf][q]);
#pragma unroll
        for (int nf = 0; nf < 8; ++nf) {
            split32(curb[nf][0], bhi[nf][0], blo[nf][0]);
            split32(curb[nf][1], bhi[nf][1], blo[nf][1]);
        }
#pragma unroll
        for (int mf = 0; mf < 2; ++mf)
#pragma unroll
            for (int nf = 0; nf < 8; ++nf) {
                mma8(acc[mf][nf], ahi[mf], bhi[nf]);
                mma8(acc[mf][nf], ahi[mf], blo[nf]);
                mma8(acc[mf][nf], alo[mf], bhi[nf]);
            }
#pragma unroll
        for (int mf = 0; mf < 2; ++mf)
#pragma unroll
            for (int q = 0; q < 4; ++q) cura[mf][q] = nxta[mf][q];
#pragma unroll
        for (int nf = 0; nf < 8; ++nf) {
            curb[nf][0] = nxtb[nf][0];
            curb[nf][1] = nxtb[nf][1];
        }
    }

    // epilogue
#pragma unroll
    for (int mf = 0; mf < 2; ++mf) {
#pragma unroll
        for (int half = 0; half < 2; ++half) {
            int r = row0 + wm * 32 + mf * 16 + g + half * 8;
            if (r >= nrows) continue;
#pragma unroll
            for (int nf = 0; nf < 8; ++nf) {
                int col = wn * 64 + nf * 8 + 2 * tg;
                float x = acc[mf][nf][half * 2 + 0];
                float y = acc[mf][nf][half * 2 + 1];
                if (bias) { x += bias[col]; y += bias[col + 1]; }
                if (dorelu) { x = fmaxf(x, 0.f); y = fmaxf(y, 0.f); }
                if (addsrc) {
                    const float* ap = addsrc + (size_t)r * HID + col;
                    x += ap[0]; y += ap[1];
                }
                *(float2*)(out + (size_t)r * HID + col) = make_float2(x, y);
            }
        }
    }
}

// ---- stage A tile into SMEM ----
__device__ __forceinline__ void stage_A(float* As, const float* __restrict__ A,
                                        int nrows, int row0) {
    const int tid = threadIdx.x;
#pragma unroll
    for (int it = 0; it < 16; ++it) {
        int e4 = tid + it * 256;
        int r = e4 >> 5, k4 = e4 & 31;
        float4 a;
        if (row0 + r < nrows)
            a = ((const float4*)(A + (size_t)(row0 + r) * HID))[k4];
        else
            a = make_float4(0.f, 0.f, 0.f, 0.f);
        *(float4*)&As[r * APAD + 4 * k4] = a;
    }
}

// ---- fused Q/K/V projection: stage feats once, run 3 weight matrices ----
__global__ __launch_bounds__(256, 1)
void gemm_qkv(const float* __restrict__ feats, const float* __restrict__ Wq,
              const float* __restrict__ Wk, const float* __restrict__ Wv,
              float* __restrict__ q, float* __restrict__ k, float* __restrict__ v,
              int nrows) {
    extern __shared__ float smem[];
    float* As = smem;
    float* Ws = smem + 128 * APAD;
    int row0 = blockIdx.x * 128;
    stage_A(As, feats, nrows, row0);
    gemm_core(As, Ws, Wq, nullptr, nullptr, q, nrows, row0, 0);
    gemm_core(As, Ws, Wk, nullptr, nullptr, k, nrows, row0, 0);
    gemm_core(As, Ws, Wv, nullptr, nullptr, v, nrows, row0, 0);
}

// ---- single GEMM (for W1, W2) ----
__global__ __launch_bounds__(256, 1)
void gemm_one(const float* __restrict__ A, const float* __restrict__ W,
              const float* __restrict__ bias, const float* __restrict__ addsrc,
              float* __restrict__ out, int nrows, int dorelu) {
    extern __shared__ float smem[];
    float* As = smem;
    float* Ws = smem + 128 * APAD;
    int row0 = blockIdx.x * 128;
    stage_A(As, A, nrows, row0);
    gemm_core(As, Ws, W, bias, addsrc, out, nrows, row0, dorelu);
}

// ---- fused attention + aggregation, warp per destination node --------------------
// agg[n] = sum_e exp(lrelu(q[kj_e].k[n]))*v[kj_e] / sum_e exp(lrelu(q[kj_e].k[n]))
__global__ void att_agg_kernel(const void* __restrict__ idx_kj) {
    int n = (blockIdx.x * blockDim.x + threadIdx.x) >> 5;
    if (n >= NROWS) return;
    int lane = threadIdx.x & 31;
    bool is64 = (g_is64 != 0);

    int start = g_hist[n], end = g_hist[n + 1];
    float4 kv = ((const float4*)g_k)[(size_t)n * 32 + lane];
    float4 acc = make_float4(0.f, 0.f, 0.f, 0.f);
    float denom = 0.f;

    for (int p = start; p < end; ++p) {
        int e = g_perm[p];
        long long kj = load_idx(idx_kj, e, is64);
        float4 qv = ((const float4*)g_q)[kj * 32 + lane];
        float4 vv = ((const float4*)g_v)[kj * 32 + lane];
        float d = qv.x * kv.x + qv.y * kv.y + qv.z * kv.z + qv.w * kv.w;
        d += __shfl_xor_sync(0xffffffffu, d, 1);
        d += __shfl_xor_sync(0xffffffffu, d, 2);
        float s = d > 0.f ? d : 0.2f * d;     // leaky_relu(0.2)
        float a = expf(s);
        denom += a;
        acc.x += a * vv.x; acc.y += a * vv.y;
        acc.z += a * vv.z; acc.w += a * vv.w;
    }

    float inv = (end > start) ? 1.f / denom : 0.f;
    float4 o = make_float4(acc.x * inv, acc.y * inv, acc.z * inv, acc.w * inv);
    ((float4*)g_agg)[(size_t)n * 32 + lane] = o;
}

// ---------------- launch ----------------
extern "C" void kernel_launch(void* const* d_in, const int* in_sizes, int n_in,
                              void* d_out, int out_size) {
    const float* feats = (const float*)d_in[0];
    const void*  idx_kj = d_in[1];
    const void*  idx_ji = d_in[2];
    const float* Wv = (const float*)d_in[3];
    const float* Wq = (const float*)d_in[4];
    const float* Wk = (const float*)d_in[5];
    const float* W1 = (const float*)d_in[6];
    const float* b1 = (const float*)d_in[7];
    const float* W2 = (const float*)d_in[8];
    const float* b2 = (const float*)d_in[9];
    float* out = (float*)d_out;

    int nrows = in_sizes[0] / HID;
    int m     = in_sizes[1];

    float *q_p, *k_p, *v_p, *agg_p, *h1_p;
    cudaGetSymbolAddress((void**)&q_p,   g_q);
    cudaGetSymbolAddress((void**)&k_p,   g_k);
    cudaGetSymbolAddress((void**)&v_p,   g_v);
    cudaGetSymbolAddress((void**)&agg_p, g_agg);
    cudaGetSymbolAddress((void**)&h1_p,  g_h1);

    cudaFuncSetAttribute(gemm_qkv, cudaFuncAttributeMaxDynamicSharedMemorySize,
                         GEMM_SMEM);
    cudaFuncSetAttribute(gemm_one, cudaFuncAttributeMaxDynamicSharedMemorySize,
                         GEMM_SMEM);

    // sort triplets by destination
    detect_kernel<<<1, 256>>>((const unsigned int*)idx_kj, m);
    zero_hist<<<256, 256>>>();
    hist_kernel<<<1024, 256>>>(idx_ji, m);
    scan1_kernel<<<NBLK, 1024>>>();
    scan2_kernel<<<1, 1>>>();
    scan3_kernel<<<256, 256>>>();
    scatter_kernel<<<1024, 256>>>(idx_ji, m);

    int gblocks = (nrows + 127) / 128;
    gemm_qkv<<<gblocks, 256, GEMM_SMEM>>>(feats, Wq, Wk, Wv, q_p, k_p, v_p, nrows);

    int ablocks = (NROWS * 32 + 255) / 256;
    att_agg_kernel<<<ablocks, 256>>>(idx_kj);

    gemm_one<<<gblocks, 256, GEMM_SMEM>>>(agg_p, W1, b1, nullptr, h1_p, nrows, 1);
    gemm_one<<<gblocks, 256, GEMM_SMEM>>>(h1_p, W2, b2, v_p, out, nrows, 1);
}

// round 5
// speedup vs baseline: 1.6209x; 1.2595x over previous
#include <cuda_runtime.h>
#include <math.h>
#include <stdint.h>

#define NROWS 100000
#define MTRIP 800000
#define HID   128
#define HEADS 8
#define APAD  132
#define NBLK  ((NROWS + 1023) / 1024)
// As: 64 rows, Ws: 128 rows
#define GEMM_SMEM (((64 + 128) * APAD) * 4)

// ---------------- scratch (static device globals; no allocs allowed) ----------------
__device__ float g_q[NROWS * HID];
__device__ float g_k[NROWS * HID];
__device__ float g_v[NROWS * HID];
__device__ float g_agg[NROWS * HID];
__device__ float g_h1[NROWS * HID];
__device__ int   g_hist[NROWS + 1];   // exclusive segment offsets after scan
__device__ int   g_cursor[NROWS];
__device__ int   g_bsums[NBLK];
__device__ int   g_perm[MTRIP];       // stores source index kj, dest-sorted
__device__ int   g_is64;

// ---------------- index dtype detection ----------------
__global__ void detect_kernel(const unsigned int* raw, int m) {
    __shared__ int nz;
    if (threadIdx.x == 0) nz = 0;
    __syncthreads();
    int c = m < 2048 ? m : 2048;
    int local = 0;
    for (int i = threadIdx.x; i < c; i += blockDim.x)
        if (raw[2 * i + 1] != 0u) local = 1;
    if (local) atomicOr(&nz, 1);
    __syncthreads();
    if (threadIdx.x == 0) g_is64 = (nz == 0) ? 1 : 0;
}

__device__ __forceinline__ long long load_idx(const void* p, int i, bool is64) {
    return is64 ? ((const long long*)p)[i] : (long long)((const int*)p)[i];
}

// ---------------- counting sort by destination (idx_ji) ----------------
__global__ void zero_hist() {
    for (int i = blockIdx.x * blockDim.x + threadIdx.x; i <= NROWS;
         i += gridDim.x * blockDim.x)
        g_hist[i] = 0;
}

__global__ void hist_kernel(const void* __restrict__ idx_ji, int m) {
    bool is64 = (g_is64 != 0);
    for (int e = blockIdx.x * blockDim.x + threadIdx.x; e < m;
         e += gridDim.x * blockDim.x)
        atomicAdd(&g_hist[(int)load_idx(idx_ji, e, is64)], 1);
}

__global__ void scan1_kernel() {
    __shared__ int s[1024];
    int t = threadIdx.x;
    int i = blockIdx.x * 1024 + t;
    int v = (i < NROWS) ? g_hist[i] : 0;
    s[t] = v;
    __syncthreads();
#pragma unroll
    for (int off = 1; off < 1024; off <<= 1) {
        int x = (t >= off) ? s[t - off] : 0;
        __syncthreads();
        s[t] += x;
        __syncthreads();
    }
    if (i < NROWS) g_hist[i] = s[t] - v;   // exclusive within block
    if (t == 1023) g_bsums[blockIdx.x] = s[t];
}

__global__ void scan2_kernel() {
    int running = 0;
    for (int b = 0; b < NBLK; ++b) {
        int t = g_bsums[b];
        g_bsums[b] = running;
        running += t;
    }
    g_hist[NROWS] = running;   // = M
}

__global__ void scan3_kernel() {
    for (int i = blockIdx.x * blockDim.x + threadIdx.x; i < NROWS;
         i += gridDim.x * blockDim.x) {
        int v = g_hist[i] + g_bsums[i >> 10];
        g_hist[i] = v;
        g_cursor[i] = v;
    }
}

// scatter the SOURCE index (kj) into destination-sorted order
__global__ void scatter_kernel(const void* __restrict__ idx_ji,
                               const void* __restrict__ idx_kj, int m) {
    bool is64 = (g_is64 != 0);
    for (int e = blockIdx.x * blockDim.x + threadIdx.x; e < m;
         e += gridDim.x * blockDim.x) {
        int d = (int)load_idx(idx_ji, e, is64);
        int src = (int)load_idx(idx_kj, e, is64);
        int pos = atomicAdd(&g_cursor[d], 1);
        g_perm[pos] = src;
    }
}

// ================== tf32x3 GEMM core via mma.sync, pipelined, 2 CTA/SM =============
// Tile: 64 rows x 128 cols, 256 threads (8 warps), warp tile 32x32.
__device__ __forceinline__ uint32_t f2tf32(float f) {
    uint32_t u;
    asm("cvt.rna.tf32.f32 %0, %1;" : "=r"(u) : "f"(f));
    return u;
}
__device__ __forceinline__ void split32(float a, uint32_t& hi, uint32_t& lo) {
    hi = f2tf32(a);
    lo = f2tf32(a - __uint_as_float(hi));
}
__device__ __forceinline__ void mma8(float c[4], const uint32_t a[4], const uint32_t b[2]) {
    asm volatile(
        "mma.sync.aligned.m16n8k8.row.col.f32.tf32.tf32.f32 "
        "{%0,%1,%2,%3}, {%4,%5,%6,%7}, {%8,%9}, {%0,%1,%2,%3};"
        : "+f"(c[0]), "+f"(c[1]), "+f"(c[2]), "+f"(c[3])
        : "r"(a[0]), "r"(a[1]), "r"(a[2]), "r"(a[3]), "r"(b[0]), "r"(b[1]));
}

#define LOAD_FRAGS(fa, fb, k0)                                            \
    {                                                                     \
        _Pragma("unroll") for (int mf = 0; mf < 2; ++mf) {                \
            int br = wm * 32 + mf * 16;                                   \
            fa[mf][0] = As[(br + g) * APAD + (k0) + tg];                  \
            fa[mf][1] = As[(br + g + 8) * APAD + (k0) + tg];              \
            fa[mf][2] = As[(br + g) * APAD + (k0) + tg + 4];              \
            fa[mf][3] = As[(br + g + 8) * APAD + (k0) + tg + 4];          \
        }                                                                 \
        _Pragma("unroll") for (int nf = 0; nf < 4; ++nf) {                \
            int col = wn * 32 + nf * 8 + g;                               \
            fb[nf][0] = Ws[col * APAD + (k0) + tg];                       \
            fb[nf][1] = Ws[col * APAD + (k0) + tg + 4];                   \
        }                                                                 \
    }

__device__ __noinline__ void gemm_core(float* As, float* Ws,
                                       const float* __restrict__ W,
                                       const float* __restrict__ bias,
                                       const float* __restrict__ addsrc,
                                       float* __restrict__ out,
                                       int nrows, int row0, int dorelu) {
    const int tid = threadIdx.x;
    const int lane = tid & 31;
    const int wid = tid >> 5;
    const int wm = wid & 1, wn = wid >> 1;   // warp tile 32x32; 2 row x 4 col blocks
    const int g = lane >> 2, tg = lane & 3;

    __syncthreads();   // previous consumers of Ws done
#pragma unroll
    for (int it = 0; it < 16; ++it) {
        int e4 = tid + it * 256;
        int r = e4 >> 5, k4 = e4 & 31;
        *(float4*)&Ws[r * APAD + 4 * k4] = ((const float4*)W)[e4];
    }
    __syncthreads();

    float acc[2][4][4];
#pragma unroll
    for (int i = 0; i < 2; ++i)
#pragma unroll
        for (int j = 0; j < 4; ++j)
#pragma unroll
            for (int q = 0; q < 4; ++q) acc[i][j][q] = 0.f;

    float cura[2][4], curb[4][2], nxta[2][4], nxtb[4][2];
    LOAD_FRAGS(cura, curb, 0)

#pragma unroll 4
    for (int ks = 0; ks < 16; ++ks) {
        if (ks < 15) LOAD_FRAGS(nxta, nxtb, (ks + 1) * 8)

        uint32_t ahi[2][4], alo[2][4], bhi[4][2], blo[4][2];
#pragma unroll
        for (int mf = 0; mf < 2; ++mf)
#pragma unroll
            for (int q = 0; q < 4; ++q)
                split32(cura[mf][q], ahi[mf][q], alo[mf][q]);
#pragma unroll
        for (int nf = 0; nf < 4; ++nf) {
            split32(curb[nf][0], bhi[nf][0], blo[nf][0]);
            split32(curb[nf][1], bhi[nf][1], blo[nf][1]);
        }
#pragma unroll
        for (int mf = 0; mf < 2; ++mf)
#pragma unroll
            for (int nf = 0; nf < 4; ++nf) {
                mma8(acc[mf][nf], ahi[mf], bhi[nf]);
                mma8(acc[mf][nf], ahi[mf], blo[nf]);
                mma8(acc[mf][nf], alo[mf], bhi[nf]);
            }
#pragma unroll
        for (int mf = 0; mf < 2; ++mf)
#pragma unroll
            for (int q = 0; q < 4; ++q) cura[mf][q] = nxta[mf][q];
#pragma unroll
        for (int nf = 0; nf < 4; ++nf) {
            curb[nf][0] = nxtb[nf][0];
            curb[nf][1] = nxtb[nf][1];
        }
    }

    // epilogue
#pragma unroll
    for (int mf = 0; mf < 2; ++mf) {
#pragma unroll
        for (int half = 0; half < 2; ++half) {
            int r = row0 + wm * 32 + mf * 16 + g + half * 8;
            if (r >= nrows) continue;
#pragma unroll
            for (int nf = 0; nf < 4; ++nf) {
                int col = wn * 32 + nf * 8 + 2 * tg;
                float x = acc[mf][nf][half * 2 + 0];
                float y = acc[mf][nf][half * 2 + 1];
                if (bias) { x += bias[col]; y += bias[col + 1]; }
                if (dorelu) { x = fmaxf(x, 0.f); y = fmaxf(y, 0.f); }
                if (addsrc) {
                    const float* ap = addsrc + (size_t)r * HID + col;
                    x += ap[0]; y += ap[1];
                }
                *(float2*)(out + (size_t)r * HID + col) = make_float2(x, y);
            }
        }
    }
}

// ---- stage 64-row A tile into SMEM ----
__device__ __forceinline__ void stage_A(float* As, const float* __restrict__ A,
                                        int nrows, int row0) {
    const int tid = threadIdx.x;
#pragma unroll
    for (int it = 0; it < 8; ++it) {
        int e4 = tid + it * 256;
        int r = e4 >> 5, k4 = e4 & 31;
        float4 a;
        if (row0 + r < nrows)
            a = ((const float4*)(A + (size_t)(row0 + r) * HID))[k4];
        else
            a = make_float4(0.f, 0.f, 0.f, 0.f);
        *(float4*)&As[r * APAD + 4 * k4] = a;
    }
}

// ---- fused Q/K/V projection ----
__global__ __launch_bounds__(256, 2)
void gemm_qkv(const float* __restrict__ feats, const float* __restrict__ Wq,
              const float* __restrict__ Wk, const float* __restrict__ Wv,
              float* __restrict__ q, float* __restrict__ k, float* __restrict__ v,
              int nrows) {
    extern __shared__ float smem[];
    float* As = smem;
    float* Ws = smem + 64 * APAD;
    int row0 = blockIdx.x * 64;
    stage_A(As, feats, nrows, row0);
    gemm_core(As, Ws, Wq, nullptr, nullptr, q, nrows, row0, 0);
    gemm_core(As, Ws, Wk, nullptr, nullptr, k, nrows, row0, 0);
    gemm_core(As, Ws, Wv, nullptr, nullptr, v, nrows, row0, 0);
}

// ---- single GEMM (for W1, W2) ----
__global__ __launch_bounds__(256, 2)
void gemm_one(const float* __restrict__ A, const float* __restrict__ W,
              const float* __restrict__ bias, const float* __restrict__ addsrc,
              float* __restrict__ out, int nrows, int dorelu) {
    extern __shared__ float smem[];
    float* As = smem;
    float* Ws = smem + 64 * APAD;
    int row0 = blockIdx.x * 64;
    stage_A(As, A, nrows, row0);
    gemm_core(As, Ws, W, bias, addsrc, out, nrows, row0, dorelu);
}

// ---- fused attention + aggregation, warp per destination node --------------------
__global__ void att_agg_kernel() {
    int n = (blockIdx.x * blockDim.x + threadIdx.x) >> 5;
    if (n >= NROWS) return;
    int lane = threadIdx.x & 31;

    int start = g_hist[n], end = g_hist[n + 1];
    float4 kv = ((const float4*)g_k)[(size_t)n * 32 + lane];
    float4 acc = make_float4(0.f, 0.f, 0.f, 0.f);
    float denom = 0.f;

    int p = start;
    int kj = (p < end) ? __ldg(&g_perm[p]) : 0;
    while (p < end) {
        int kj_next = (p + 1 < end) ? __ldg(&g_perm[p + 1]) : 0;
        float4 qv = ((const float4*)g_q)[(size_t)kj * 32 + lane];
        float4 vv = ((const float4*)g_v)[(size_t)kj * 32 + lane];
        float d = qv.x * kv.x + qv.y * kv.y + qv.z * kv.z + qv.w * kv.w;
        d += __shfl_xor_sync(0xffffffffu, d, 1);
        d += __shfl_xor_sync(0xffffffffu, d, 2);
        float s = d > 0.f ? d : 0.2f * d;     // leaky_relu(0.2)
        float a = expf(s);
        denom += a;
        acc.x += a * vv.x; acc.y += a * vv.y;
        acc.z += a * vv.z; acc.w += a * vv.w;
        kj = kj_next;
        ++p;
    }

    float inv = (end > start) ? 1.f / denom : 0.f;
    float4 o = make_float4(acc.x * inv, acc.y * inv, acc.z * inv, acc.w * inv);
    ((float4*)g_agg)[(size_t)n * 32 + lane] = o;
}

// ---------------- launch ----------------
extern "C" void kernel_launch(void* const* d_in, const int* in_sizes, int n_in,
                              void* d_out, int out_size) {
    const float* feats = (const float*)d_in[0];
    const void*  idx_kj = d_in[1];
    const void*  idx_ji = d_in[2];
    const float* Wv = (const float*)d_in[3];
    const float* Wq = (const float*)d_in[4];
    const float* Wk = (const float*)d_in[5];
    const float* W1 = (const float*)d_in[6];
    const float* b1 = (const float*)d_in[7];
    const float* W2 = (const float*)d_in[8];
    const float* b2 = (const float*)d_in[9];
    float* out = (float*)d_out;

    int nrows = in_sizes[0] / HID;
    int m     = in_sizes[1];

    float *q_p, *k_p, *v_p, *agg_p, *h1_p;
    cudaGetSymbolAddress((void**)&q_p,   g_q);
    cudaGetSymbolAddress((void**)&k_p,   g_k);
    cudaGetSymbolAddress((void**)&v_p,   g_v);
    cudaGetSymbolAddress((void**)&agg_p, g_agg);
    cudaGetSymbolAddress((void**)&h1_p,  g_h1);

    cudaFuncSetAttribute(gemm_qkv, cudaFuncAttributeMaxDynamicSharedMemorySize,
                         GEMM_SMEM);
    cudaFuncSetAttribute(gemm_one, cudaFuncAttributeMaxDynamicSharedMemorySize,
                         GEMM_SMEM);

    // sort triplets by destination
    detect_kernel<<<1, 256>>>((const unsigned int*)idx_kj, m);
    zero_hist<<<256, 256>>>();
    hist_kernel<<<1024, 256>>>(idx_ji, m);
    scan1_kernel<<<NBLK, 1024>>>();
    scan2_kernel<<<1, 1>>>();
    scan3_kernel<<<256, 256>>>();
    scatter_kernel<<<1024, 256>>>(idx_ji, idx_kj, m);

    int gblocks = (nrows + 63) / 64;
    gemm_qkv<<<gblocks, 256, GEMM_SMEM>>>(feats, Wq, Wk, Wv, q_p, k_p, v_p, nrows);

    int ablocks = (NROWS * 32 + 255) / 256;
    att_agg_kernel<<<ablocks, 256>>>();

    gemm_one<<<gblocks, 256, GEMM_SMEM>>>(agg_p, W1, b1, nullptr, h1_p, nrows, 1);
    gemm_one<<<gblocks, 256, GEMM_SMEM>>>(h1_p, W2, b2, v_p, out, nrows, 1);
}

// round 6
// speedup vs baseline: 1.6984x; 1.0478x over previous
#include <cuda_runtime.h>
#include <math.h>
#include <stdint.h>

#define NROWS 100000
#define MTRIP 800000
#define HID   128
#define HEADS 8
#define APAD  132
#define NBLK  ((NROWS + 1023) / 1024)
// As: 64 rows, Ws: 128 rows
#define GEMM_SMEM (((64 + 128) * APAD) * 4)

// ---------------- scratch (static device globals; no allocs allowed) ----------------
__device__ float g_q[NROWS * HID];
__device__ float g_k[NROWS * HID];
__device__ float g_v[NROWS * HID];
__device__ float g_agg[NROWS * HID];
__device__ int   g_hist[NROWS + 1];   // exclusive segment offsets after scan
__device__ int   g_cursor[NROWS];
__device__ int   g_bsums[NBLK];
__device__ int   g_perm[MTRIP];       // stores source index kj, dest-sorted
__device__ int   g_is64;

// ---------------- index dtype detection ----------------
__global__ void detect_kernel(const unsigned int* raw, int m) {
    __shared__ int nz;
    if (threadIdx.x == 0) nz = 0;
    __syncthreads();
    int c = m < 2048 ? m : 2048;
    int local = 0;
    for (int i = threadIdx.x; i < c; i += blockDim.x)
        if (raw[2 * i + 1] != 0u) local = 1;
    if (local) atomicOr(&nz, 1);
    __syncthreads();
    if (threadIdx.x == 0) g_is64 = (nz == 0) ? 1 : 0;
}

__device__ __forceinline__ long long load_idx(const void* p, int i, bool is64) {
    return is64 ? ((const long long*)p)[i] : (long long)((const int*)p)[i];
}

// ---------------- counting sort by destination (idx_ji) ----------------
__global__ void zero_hist() {
    for (int i = blockIdx.x * blockDim.x + threadIdx.x; i <= NROWS;
         i += gridDim.x * blockDim.x)
        g_hist[i] = 0;
}

__global__ void hist_kernel(const void* __restrict__ idx_ji, int m) {
    bool is64 = (g_is64 != 0);
    for (int e = blockIdx.x * blockDim.x + threadIdx.x; e < m;
         e += gridDim.x * blockDim.x)
        atomicAdd(&g_hist[(int)load_idx(idx_ji, e, is64)], 1);
}

__global__ void scan1_kernel() {
    __shared__ int s[1024];
    int t = threadIdx.x;
    int i = blockIdx.x * 1024 + t;
    int v = (i < NROWS) ? g_hist[i] : 0;
    s[t] = v;
    __syncthreads();
#pragma unroll
    for (int off = 1; off < 1024; off <<= 1) {
        int x = (t >= off) ? s[t - off] : 0;
        __syncthreads();
        s[t] += x;
        __syncthreads();
    }
    if (i < NROWS) g_hist[i] = s[t] - v;   // exclusive within block
    if (t == 1023) g_bsums[blockIdx.x] = s[t];
}

__global__ void scan2_kernel() {
    int running = 0;
    for (int b = 0; b < NBLK; ++b) {
        int t = g_bsums[b];
        g_bsums[b] = running;
        running += t;
    }
    g_hist[NROWS] = running;   // = M
}

__global__ void scan3_kernel() {
    for (int i = blockIdx.x * blockDim.x + threadIdx.x; i < NROWS;
         i += gridDim.x * blockDim.x) {
        int v = g_hist[i] + g_bsums[i >> 10];
        g_hist[i] = v;
        g_cursor[i] = v;
    }
}

// scatter the SOURCE index (kj) into destination-sorted order
__global__ void scatter_kernel(const void* __restrict__ idx_ji,
                               const void* __restrict__ idx_kj, int m) {
    bool is64 = (g_is64 != 0);
    for (int e = blockIdx.x * blockDim.x + threadIdx.x; e < m;
         e += gridDim.x * blockDim.x) {
        int d = (int)load_idx(idx_ji, e, is64);
        int src = (int)load_idx(idx_kj, e, is64);
        int pos = atomicAdd(&g_cursor[d], 1);
        g_perm[pos] = src;
    }
}

// ================== tf32x3 GEMM core via mma.sync, pipelined, 2 CTA/SM =============
// Tile: 64 rows x 128 cols, 256 threads (8 warps), warp tile 32x32.
__device__ __forceinline__ uint32_t f2tf32(float f) {
    uint32_t u;
    asm("cvt.rna.tf32.f32 %0, %1;" : "=r"(u) : "f"(f));
    return u;
}
__device__ __forceinline__ void split32(float a, uint32_t& hi, uint32_t& lo) {
    hi = f2tf32(a);
    lo = f2tf32(a - __uint_as_float(hi));
}
__device__ __forceinline__ void mma8(float c[4], const uint32_t a[4], const uint32_t b[2]) {
    asm volatile(
        "mma.sync.aligned.m16n8k8.row.col.f32.tf32.tf32.f32 "
        "{%0,%1,%2,%3}, {%4,%5,%6,%7}, {%8,%9}, {%0,%1,%2,%3};"
        : "+f"(c[0]), "+f"(c[1]), "+f"(c[2]), "+f"(c[3])
        : "r"(a[0]), "r"(a[1]), "r"(a[2]), "r"(a[3]), "r"(b[0]), "r"(b[1]));
}

#define LOAD_FRAGS(fa, fb, k0)                                            \
    {                                                                     \
        _Pragma("unroll") for (int mf = 0; mf < 2; ++mf) {                \
            int br = wm * 32 + mf * 16;                                   \
            fa[mf][0] = As[(br + g) * APAD + (k0) + tg];                  \
            fa[mf][1] = As[(br + g + 8) * APAD + (k0) + tg];              \
            fa[mf][2] = As[(br + g) * APAD + (k0) + tg + 4];              \
            fa[mf][3] = As[(br + g + 8) * APAD + (k0) + tg + 4];          \
        }                                                                 \
        _Pragma("unroll") for (int nf = 0; nf < 4; ++nf) {                \
            int col = wn * 32 + nf * 8 + g;                               \
            fb[nf][0] = Ws[col * APAD + (k0) + tg];                       \
            fb[nf][1] = Ws[col * APAD + (k0) + tg + 4];                   \
        }                                                                 \
    }

// Core: stages W, runs 16 k-steps of tf32x3 MMA.
// mode 0: write out rows (optional bias/relu/addsrc)
// mode 1: write relu(x + bias) back into As (SMEM) -- for fused MLP middle layer
__device__ __noinline__ void gemm_core(float* As, float* Ws,
                                       const float* __restrict__ W,
                                       const float* __restrict__ bias,
                                       const float* __restrict__ addsrc,
                                       float* __restrict__ out,
                                       int nrows, int row0, int dorelu, int mode) {
    const int tid = threadIdx.x;
    const int lane = tid & 31;
    const int wid = tid >> 5;
    const int wm = wid & 1, wn = wid >> 1;   // warp tile 32x32; 2 row x 4 col blocks
    const int g = lane >> 2, tg = lane & 3;

    __syncthreads();   // previous consumers of Ws done
#pragma unroll
    for (int it = 0; it < 16; ++it) {
        int e4 = tid + it * 256;
        int r = e4 >> 5, k4 = e4 & 31;
        *(float4*)&Ws[r * APAD + 4 * k4] = ((const float4*)W)[e4];
    }
    __syncthreads();

    float acc[2][4][4];
#pragma unroll
    for (int i = 0; i < 2; ++i)
#pragma unroll
        for (int j = 0; j < 4; ++j)
#pragma unroll
            for (int q = 0; q < 4; ++q) acc[i][j][q] = 0.f;

    float cura[2][4], curb[4][2], nxta[2][4], nxtb[4][2];
    LOAD_FRAGS(cura, curb, 0)

#pragma unroll 4
    for (int ks = 0; ks < 16; ++ks) {
        if (ks < 15) LOAD_FRAGS(nxta, nxtb, (ks + 1) * 8)

        uint32_t ahi[2][4], alo[2][4], bhi[4][2], blo[4][2];
#pragma unroll
        for (int mf = 0; mf < 2; ++mf)
#pragma unroll
            for (int q = 0; q < 4; ++q)
                split32(cura[mf][q], ahi[mf][q], alo[mf][q]);
#pragma unroll
        for (int nf = 0; nf < 4; ++nf) {
            split32(curb[nf][0], bhi[nf][0], blo[nf][0]);
            split32(curb[nf][1], bhi[nf][1], blo[nf][1]);
        }
#pragma unroll
        for (int mf = 0; mf < 2; ++mf)
#pragma unroll
            for (int nf = 0; nf < 4; ++nf) {
                mma8(acc[mf][nf], ahi[mf], bhi[nf]);
                mma8(acc[mf][nf], ahi[mf], blo[nf]);
                mma8(acc[mf][nf], alo[mf], bhi[nf]);
            }
#pragma unroll
        for (int mf = 0; mf < 2; ++mf)
#pragma unroll
            for (int q = 0; q < 4; ++q) cura[mf][q] = nxta[mf][q];
#pragma unroll
        for (int nf = 0; nf < 4; ++nf) {
            curb[nf][0] = nxtb[nf][0];
            curb[nf][1] = nxtb[nf][1];
        }
    }

    if (mode == 1) {
        // fused-MLP middle layer: h = relu(x + bias) -> back into As
        __syncthreads();   // all warps done reading As
#pragma unroll
        for (int mf = 0; mf < 2; ++mf) {
#pragma unroll
            for (int half = 0; half < 2; ++half) {
                int rl = wm * 32 + mf * 16 + g + half * 8;
#pragma unroll
                for (int nf = 0; nf < 4; ++nf) {
                    int col = wn * 32 + nf * 8 + 2 * tg;
                    float x = acc[mf][nf][half * 2 + 0] + bias[col];
                    float y = acc[mf][nf][half * 2 + 1] + bias[col + 1];
                    As[rl * APAD + col]     = fmaxf(x, 0.f);
                    As[rl * APAD + col + 1] = fmaxf(y, 0.f);
                }
            }
        }
        return;   // caller's next gemm_core starts with __syncthreads()
    }

    // epilogue to gmem
#pragma unroll
    for (int mf = 0; mf < 2; ++mf) {
#pragma unroll
        for (int half = 0; half < 2; ++half) {
            int r = row0 + wm * 32 + mf * 16 + g + half * 8;
            if (r >= nrows) continue;
#pragma unroll
            for (int nf = 0; nf < 4; ++nf) {
                int col = wn * 32 + nf * 8 + 2 * tg;
                float x = acc[mf][nf][half * 2 + 0];
                float y = acc[mf][nf][half * 2 + 1];
                if (bias) { x += bias[col]; y += bias[col + 1]; }
                if (dorelu) { x = fmaxf(x, 0.f); y = fmaxf(y, 0.f); }
                if (addsrc) {
                    const float* ap = addsrc + (size_t)r * HID + col;
                    x += ap[0]; y += ap[1];
                }
                *(float2*)(out + (size_t)r * HID + col) = make_float2(x, y);
            }
        }
    }
}

// ---- stage 64-row A tile into SMEM ----
__device__ __forceinline__ void stage_A(float* As, const float* __restrict__ A,
                                        int nrows, int row0) {
    const int tid = threadIdx.x;
#pragma unroll
    for (int it = 0; it < 8; ++it) {
        int e4 = tid + it * 256;
        int r = e4 >> 5, k4 = e4 & 31;
        float4 a;
        if (row0 + r < nrows)
            a = ((const float4*)(A + (size_t)(row0 + r) * HID))[k4];
        else
            a = make_float4(0.f, 0.f, 0.f, 0.f);
        *(float4*)&As[r * APAD + 4 * k4] = a;
    }
}

// ---- fused Q/K/V projection ----
__global__ __launch_bounds__(256, 2)
void gemm_qkv(const float* __restrict__ feats, const float* __restrict__ Wq,
              const float* __restrict__ Wk, const float* __restrict__ Wv,
              float* __restrict__ q, float* __restrict__ k, float* __restrict__ v,
              int nrows) {
    extern __shared__ float smem[];
    float* As = smem;
    float* Ws = smem + 64 * APAD;
    int row0 = blockIdx.x * 64;
    stage_A(As, feats, nrows, row0);
    gemm_core(As, Ws, Wq, nullptr, nullptr, q, nrows, row0, 0, 0);
    gemm_core(As, Ws, Wk, nullptr, nullptr, k, nrows, row0, 0, 0);
    gemm_core(As, Ws, Wv, nullptr, nullptr, v, nrows, row0, 0, 0);
}

// ---- fused MLP: out = v + relu(W2 @ relu(W1 @ agg + b1) + b2) ----
__global__ __launch_bounds__(256, 2)
void gemm_mlp(const float* __restrict__ agg,
              const float* __restrict__ W1, const float* __restrict__ b1,
              const float* __restrict__ W2, const float* __restrict__ b2,
              const float* __restrict__ v, float* __restrict__ out, int nrows) {
    extern __shared__ float smem[];
    float* As = smem;
    float* Ws = smem + 64 * APAD;
    int row0 = blockIdx.x * 64;
    stage_A(As, agg, nrows, row0);
    gemm_core(As, Ws, W1, b1, nullptr, nullptr, nrows, row0, 1, 1);   // h -> As
    gemm_core(As, Ws, W2, b2, v, out, nrows, row0, 1, 0);
}

// ---- fused attention + aggregation, warp per destination node --------------------
__global__ void att_agg_kernel() {
    int n = (blockIdx.x * blockDim.x + threadIdx.x) >> 5;
    if (n >= NROWS) return;
    int lane = threadIdx.x & 31;

    int start = g_hist[n], end = g_hist[n + 1];
    float4 kv = ((const float4*)g_k)[(size_t)n * 32 + lane];
    float4 acc = make_float4(0.f, 0.f, 0.f, 0.f);
    float denom = 0.f;

    int p = start;
    int kj = (p < end) ? __ldg(&g_perm[p]) : 0;
    while (p < end) {
        int kj_next = (p + 1 < end) ? __ldg(&g_perm[p + 1]) : 0;
        float4 qv = ((const float4*)g_q)[(size_t)kj * 32 + lane];
        float4 vv = ((const float4*)g_v)[(size_t)kj * 32 + lane];
        float d = qv.x * kv.x + qv.y * kv.y + qv.z * kv.z + qv.w * kv.w;
        d += __shfl_xor_sync(0xffffffffu, d, 1);
        d += __shfl_xor_sync(0xffffffffu, d, 2);
        float s = d > 0.f ? d : 0.2f * d;     // leaky_relu(0.2)
        float a = expf(s);
        denom += a;
        acc.x += a * vv.x; acc.y += a * vv.y;
        acc.z += a * vv.z; acc.w += a * vv.w;
        kj = kj_next;
        ++p;
    }

    float inv = (end > start) ? 1.f / denom : 0.f;
    float4 o = make_float4(acc.x * inv, acc.y * inv, acc.z * inv, acc.w * inv);
    ((float4*)g_agg)[(size_t)n * 32 + lane] = o;
}

// ---------------- launch ----------------
extern "C" void kernel_launch(void* const* d_in, const int* in_sizes, int n_in,
                              void* d_out, int out_size) {
    const float* feats = (const float*)d_in[0];
    const void*  idx_kj = d_in[1];
    const void*  idx_ji = d_in[2];
    const float* Wv = (const float*)d_in[3];
    const float* Wq = (const float*)d_in[4];
    const float* Wk = (const float*)d_in[5];
    const float* W1 = (const float*)d_in[6];
    const float* b1 = (const float*)d_in[7];
    const float* W2 = (const float*)d_in[8];
    const float* b2 = (const float*)d_in[9];
    float* out = (float*)d_out;

    int nrows = in_sizes[0] / HID;
    int m     = in_sizes[1];

    float *q_p, *k_p, *v_p, *agg_p;
    cudaGetSymbolAddress((void**)&q_p,   g_q);
    cudaGetSymbolAddress((void**)&k_p,   g_k);
    cudaGetSymbolAddress((void**)&v_p,   g_v);
    cudaGetSymbolAddress((void**)&agg_p, g_agg);

    cudaFuncSetAttribute(gemm_qkv, cudaFuncAttributeMaxDynamicSharedMemorySize,
                         GEMM_SMEM);
    cudaFuncSetAttribute(gemm_mlp, cudaFuncAttributeMaxDynamicSharedMemorySize,
                         GEMM_SMEM);

    // side stream + events for overlapping the sort chain with gemm_qkv
    static cudaStream_t s_side = nullptr;
    static cudaEvent_t  ev_fork = nullptr, ev_join = nullptr;
    if (!s_side) {
        cudaStreamCreateWithFlags(&s_side, cudaStreamNonBlocking);
        cudaEventCreateWithFlags(&ev_fork, cudaEventDisableTiming);
        cudaEventCreateWithFlags(&ev_join, cudaEventDisableTiming);
    }

    // fork: sort triplets by destination on the side stream
    cudaEventRecord(ev_fork, 0);
    cudaStreamWaitEvent(s_side, ev_fork, 0);
    detect_kernel<<<1, 256, 0, s_side>>>((const unsigned int*)idx_kj, m);
    zero_hist<<<256, 256, 0, s_side>>>();
    hist_kernel<<<1024, 256, 0, s_side>>>(idx_ji, m);
    scan1_kernel<<<NBLK, 1024, 0, s_side>>>();
    scan2_kernel<<<1, 1, 0, s_side>>>();
    scan3_kernel<<<256, 256, 0, s_side>>>();
    scatter_kernel<<<1024, 256, 0, s_side>>>(idx_ji, idx_kj, m);
    cudaEventRecord(ev_join, s_side);

    // main stream: QKV projections (independent of the sort)
    int gblocks = (nrows + 63) / 64;
    gemm_qkv<<<gblocks, 256, GEMM_SMEM>>>(feats, Wq, Wk, Wv, q_p, k_p, v_p, nrows);

    // join, then attention + fused MLP
    cudaStreamWaitEvent(0, ev_join, 0);
    int ablocks = (NROWS * 32 + 255) / 256;
    att_agg_kernel<<<ablocks, 256>>>();

    gemm_mlp<<<gblocks, 256, GEMM_SMEM>>>(agg_p, W1, b1, W2, b2, v_p, out, nrows);
}

// round 7
// speedup vs baseline: 2.5290x; 1.4890x over previous
#include <cuda_runtime.h>
#include <cuda_bf16.h>
#include <math.h>
#include <stdint.h>

#define NROWS 100000
#define MTRIP 800000
#define HID   128
#define HEADS 8
#define NBLK  ((NROWS + 1023) / 1024)

// packed bf16-pair words per row: 64 + pad. 68 => (g*4+tg) distinct mod 32
#define PAD2  68
// smem: As_hi, As_lo (64 rows) + Ws_hi, Ws_lo (128 rows), uint32 words
#define GEMM_SMEM ((64 * 2 + 128 * 2) * PAD2 * 4)

// ---------------- scratch (static device globals; no allocs allowed) ----------------
__device__ float g_q[NROWS * HID];
__device__ float g_k[NROWS * HID];
__device__ float g_v[NROWS * HID];
__device__ float g_agg[NROWS * HID];
__device__ int   g_hist[NROWS + 1];   // exclusive segment offsets after scan
__device__ int   g_cursor[NROWS];
__device__ int   g_bsums[NBLK];
__device__ int   g_perm[MTRIP];       // stores source index kj, dest-sorted
__device__ int   g_is64;

// ---------------- index dtype detection ----------------
__global__ void detect_kernel(const unsigned int* raw, int m) {
    __shared__ int nz;
    if (threadIdx.x == 0) nz = 0;
    __syncthreads();
    int c = m < 2048 ? m : 2048;
    int local = 0;
    for (int i = threadIdx.x; i < c; i += blockDim.x)
        if (raw[2 * i + 1] != 0u) local = 1;
    if (local) atomicOr(&nz, 1);
    __syncthreads();
    if (threadIdx.x == 0) g_is64 = (nz == 0) ? 1 : 0;
}

__device__ __forceinline__ long long load_idx(const void* p, int i, bool is64) {
    return is64 ? ((const long long*)p)[i] : (long long)((const int*)p)[i];
}

// ---------------- counting sort by destination (idx_ji) ----------------
__global__ void zero_hist() {
    for (int i = blockIdx.x * blockDim.x + threadIdx.x; i <= NROWS;
         i += gridDim.x * blockDim.x)
        g_hist[i] = 0;
}

__global__ void hist_kernel(const void* __restrict__ idx_ji, int m) {
    bool is64 = (g_is64 != 0);
    for (int e = blockIdx.x * blockDim.x + threadIdx.x; e < m;
         e += gridDim.x * blockDim.x)
        atomicAdd(&g_hist[(int)load_idx(idx_ji, e, is64)], 1);
}

__global__ void scan1_kernel() {
    __shared__ int s[1024];
    int t = threadIdx.x;
    int i = blockIdx.x * 1024 + t;
    int v = (i < NROWS) ? g_hist[i] : 0;
    s[t] = v;
    __syncthreads();
#pragma unroll
    for (int off = 1; off < 1024; off <<= 1) {
        int x = (t >= off) ? s[t - off] : 0;
        __syncthreads();
        s[t] += x;
        __syncthreads();
    }
    if (i < NROWS) g_hist[i] = s[t] - v;   // exclusive within block
    if (t == 1023) g_bsums[blockIdx.x] = s[t];
}

__global__ void scan2_kernel() {
    int running = 0;
    for (int b = 0; b < NBLK; ++b) {
        int t = g_bsums[b];
        g_bsums[b] = running;
        running += t;
    }
    g_hist[NROWS] = running;   // = M
}

__global__ void scan3_kernel() {
    for (int i = blockIdx.x * blockDim.x + threadIdx.x; i < NROWS;
         i += gridDim.x * blockDim.x) {
        int v = g_hist[i] + g_bsums[i >> 10];
        g_hist[i] = v;
        g_cursor[i] = v;
    }
}

// scatter the SOURCE index (kj) into destination-sorted order
__global__ void scatter_kernel(const void* __restrict__ idx_ji,
                               const void* __restrict__ idx_kj, int m) {
    bool is64 = (g_is64 != 0);
    for (int e = blockIdx.x * blockDim.x + threadIdx.x; e < m;
         e += gridDim.x * blockDim.x) {
        int d = (int)load_idx(idx_ji, e, is64);
        int src = (int)load_idx(idx_kj, e, is64);
        int pos = atomicAdd(&g_cursor[d], 1);
        g_perm[pos] = src;
    }
}

// ================== bf16x2 3-term GEMM via mma.sync.m16n8k16 =======================
// out[r][o] = sum_i A[r][i] * W[o][i]. A,W pre-split hi/lo bf16 pairs in SMEM.
// Tile: 64 rows x 128 cols, 256 threads (8 warps), warp tile 32x32, K=128 (8 k16 steps).

// split two fp32 (v0 = even k, v1 = odd k) into packed bf16x2 hi + lo words
__device__ __forceinline__ void split_pack(float v0, float v1,
                                           uint32_t& hi, uint32_t& lo) {
    __nv_bfloat162 h2 = __floats2bfloat162_rn(v0, v1);   // x=v0 (low), y=v1 (high)
    hi = *reinterpret_cast<uint32_t*>(&h2);
    float r0 = v0 - __bfloat162float(h2.x);
    float r1 = v1 - __bfloat162float(h2.y);
    __nv_bfloat162 l2 = __floats2bfloat162_rn(r0, r1);
    lo = *reinterpret_cast<uint32_t*>(&l2);
}

__device__ __forceinline__ void mma16(float c[4], const uint32_t a[4],
                                      const uint32_t b[2]) {
    asm volatile(
        "mma.sync.aligned.m16n8k16.row.col.f32.bf16.bf16.f32 "
        "{%0,%1,%2,%3}, {%4,%5,%6,%7}, {%8,%9}, {%0,%1,%2,%3};"
        : "+f"(c[0]), "+f"(c[1]), "+f"(c[2]), "+f"(c[3])
        : "r"(a[0]), "r"(a[1]), "r"(a[2]), "r"(a[3]), "r"(b[0]), "r"(b[1]));
}

// Core: stages W split into SMEM, runs 8 k16-steps of bf16x2 3-term MMA.
// mode 0: write out rows (optional bias/relu/addsrc)
// mode 1: write relu(x + bias) back into As_hi/As_lo (for fused MLP middle layer)
__device__ __noinline__ void gemm_core(uint32_t* As_hi, uint32_t* As_lo,
                                       uint32_t* Ws_hi, uint32_t* Ws_lo,
                                       const float* __restrict__ W,
                                       const float* __restrict__ bias,
                                       const float* __restrict__ addsrc,
                                       float* __restrict__ out,
                                       int nrows, int row0, int dorelu, int mode) {
    const int tid = threadIdx.x;
    const int lane = tid & 31;
    const int wid = tid >> 5;
    const int wm = wid & 1, wn = wid >> 1;   // warp tile 32x32
    const int g = lane >> 2, tg = lane & 3;

    __syncthreads();   // previous consumers of Ws done
    // stage W: 128 rows x 64 pairs = 8192 words
#pragma unroll
    for (int it = 0; it < 32; ++it) {
        int e = tid + it * 256;
        int o = e >> 6, p = e & 63;
        float2 w = ((const float2*)W)[e];
        uint32_t h, l;
        split_pack(w.x, w.y, h, l);
        Ws_hi[o * PAD2 + p] = h;
        Ws_lo[o * PAD2 + p] = l;
    }
    __syncthreads();

    float acc[2][4][4];
#pragma unroll
    for (int i = 0; i < 2; ++i)
#pragma unroll
        for (int j = 0; j < 4; ++j)
#pragma unroll
            for (int q = 0; q < 4; ++q) acc[i][j][q] = 0.f;

#pragma unroll
    for (int ks = 0; ks < 8; ++ks) {
        const int kp = ks * 8;
        uint32_t ah[2][4], al[2][4], bh[4][2], bl[4][2];
#pragma unroll
        for (int mf = 0; mf < 2; ++mf) {
            int br = wm * 32 + mf * 16;
            ah[mf][0] = As_hi[(br + g) * PAD2 + kp + tg];
            ah[mf][1] = As_hi[(br + g + 8) * PAD2 + kp + tg];
            ah[mf][2] = As_hi[(br + g) * PAD2 + kp + tg + 4];
            ah[mf][3] = As_hi[(br + g + 8) * PAD2 + kp + tg + 4];
            al[mf][0] = As_lo[(br + g) * PAD2 + kp + tg];
            al[mf][1] = As_lo[(br + g + 8) * PAD2 + kp + tg];
            al[mf][2] = As_lo[(br + g) * PAD2 + kp + tg + 4];
            al[mf][3] = As_lo[(br + g + 8) * PAD2 + kp + tg + 4];
        }
#pragma unroll
        for (int nf = 0; nf < 4; ++nf) {
            int col = wn * 32 + nf * 8 + g;
            bh[nf][0] = Ws_hi[col * PAD2 + kp + tg];
            bh[nf][1] = Ws_hi[col * PAD2 + kp + tg + 4];
            bl[nf][0] = Ws_lo[col * PAD2 + kp + tg];
            bl[nf][1] = Ws_lo[col * PAD2 + kp + tg + 4];
        }
#pragma unroll
        for (int mf = 0; mf < 2; ++mf)
#pragma unroll
            for (int nf = 0; nf < 4; ++nf) {
                mma16(acc[mf][nf], ah[mf], bh[nf]);
                mma16(acc[mf][nf], ah[mf], bl[nf]);
                mma16(acc[mf][nf], al[mf], bh[nf]);
            }
    }

    if (mode == 1) {
        // fused-MLP middle layer: h = relu(x + bias) -> back into As (split bf16)
        __syncthreads();   // all warps done reading As
#pragma unroll
        for (int mf = 0; mf < 2; ++mf) {
#pragma unroll
            for (int half = 0; half < 2; ++half) {
                int rl = wm * 32 + mf * 16 + g + half * 8;
#pragma unroll
                for (int nf = 0; nf < 4; ++nf) {
                    int col = wn * 32 + nf * 8 + 2 * tg;
                    float x = fmaxf(acc[mf][nf][half * 2 + 0] + bias[col], 0.f);
                    float y = fmaxf(acc[mf][nf][half * 2 + 1] + bias[col + 1], 0.f);
                    uint32_t h, l;
                    split_pack(x, y, h, l);
                    int widx = rl * PAD2 + wn * 16 + nf * 4 + tg;
                    As_hi[widx] = h;
                    As_lo[widx] = l;
                }
            }
        }
        return;   // caller's next gemm_core starts with __syncthreads()
    }

    // epilogue to gmem
#pragma unroll
    for (int mf = 0; mf < 2; ++mf) {
#pragma unroll
        for (int half = 0; half < 2; ++half) {
            int r = row0 + wm * 32 + mf * 16 + g + half * 8;
            if (r >= nrows) continue;
#pragma unroll
            for (int nf = 0; nf < 4; ++nf) {
                int col = wn * 32 + nf * 8 + 2 * tg;
                float x = acc[mf][nf][half * 2 + 0];
                float y = acc[mf][nf][half * 2 + 1];
                if (bias) { x += bias[col]; y += bias[col + 1]; }
                if (dorelu) { x = fmaxf(x, 0.f); y = fmaxf(y, 0.f); }
                if (addsrc) {
                    const float* ap = addsrc + (size_t)r * HID + col;
                    x += ap[0]; y += ap[1];
                }
                *(float2*)(out + (size_t)r * HID + col) = make_float2(x, y);
            }
        }
    }
}

// ---- stage 64-row A tile into SMEM as split bf16 pairs ----
__device__ __forceinline__ void stage_A(uint32_t* As_hi, uint32_t* As_lo,
                                        const float* __restrict__ A,
                                        int nrows, int row0) {
    const int tid = threadIdx.x;
#pragma unroll
    for (int it = 0; it < 16; ++it) {
        int e = tid + it * 256;       // 64 rows x 64 pairs = 4096 words
        int r = e >> 6, p = e & 63;
        float2 a = make_float2(0.f, 0.f);
        if (row0 + r < nrows)
            a = ((const float2*)(A + (size_t)(row0 + r) * HID))[p];
        uint32_t h, l;
        split_pack(a.x, a.y, h, l);
        As_hi[r * PAD2 + p] = h;
        As_lo[r * PAD2 + p] = l;
    }
}

// ---- fused Q/K/V projection ----
__global__ __launch_bounds__(256, 2)
void gemm_qkv(const float* __restrict__ feats, const float* __restrict__ Wq,
              const float* __restrict__ Wk, const float* __restrict__ Wv,
              float* __restrict__ q, float* __restrict__ k, float* __restrict__ v,
              int nrows) {
    extern __shared__ uint32_t smem_u[];
    uint32_t* As_hi = smem_u;
    uint32_t* As_lo = As_hi + 64 * PAD2;
    uint32_t* Ws_hi = As_lo + 64 * PAD2;
    uint32_t* Ws_lo = Ws_hi + 128 * PAD2;
    int row0 = blockIdx.x * 64;
    stage_A(As_hi, As_lo, feats, nrows, row0);
    gemm_core(As_hi, As_lo, Ws_hi, Ws_lo, Wq, nullptr, nullptr, q, nrows, row0, 0, 0);
    gemm_core(As_hi, As_lo, Ws_hi, Ws_lo, Wk, nullptr, nullptr, k, nrows, row0, 0, 0);
    gemm_core(As_hi, As_lo, Ws_hi, Ws_lo, Wv, nullptr, nullptr, v, nrows, row0, 0, 0);
}

// ---- fused MLP: out = v + relu(W2 @ relu(W1 @ agg + b1) + b2) ----
__global__ __launch_bounds__(256, 2)
void gemm_mlp(const float* __restrict__ agg,
              const float* __restrict__ W1, const float* __restrict__ b1,
              const float* __restrict__ W2, const float* __restrict__ b2,
              const float* __restrict__ v, float* __restrict__ out, int nrows) {
    extern __shared__ uint32_t smem_u[];
    uint32_t* As_hi = smem_u;
    uint32_t* As_lo = As_hi + 64 * PAD2;
    uint32_t* Ws_hi = As_lo + 64 * PAD2;
    uint32_t* Ws_lo = Ws_hi + 128 * PAD2;
    int row0 = blockIdx.x * 64;
    stage_A(As_hi, As_lo, agg, nrows, row0);
    gemm_core(As_hi, As_lo, Ws_hi, Ws_lo, W1, b1, nullptr, nullptr, nrows, row0, 1, 1);
    gemm_core(As_hi, As_lo, Ws_hi, Ws_lo, W2, b2, v, out, nrows, row0, 1, 0);
}

// ---- fused attention + aggregation, warp per destination node, 2-edge unroll ------
__global__ void att_agg_kernel() {
    int n = (blockIdx.x * blockDim.x + threadIdx.x) >> 5;
    if (n >= NROWS) return;
    int lane = threadIdx.x & 31;

    int start = g_hist[n], end = g_hist[n + 1];
    float4 kv = ((const float4*)g_k)[(size_t)n * 32 + lane];
    float4 acc = make_float4(0.f, 0.f, 0.f, 0.f);
    float denom = 0.f;

    int p = start;
    for (; p + 2 <= end; p += 2) {
        int kj0 = __ldg(&g_perm[p]);
        int kj1 = __ldg(&g_perm[p + 1]);
        float4 q0 = ((const float4*)g_q)[(size_t)kj0 * 32 + lane];
        float4 v0 = ((const float4*)g_v)[(size_t)kj0 * 32 + lane];
        float4 q1 = ((const float4*)g_q)[(size_t)kj1 * 32 + lane];
        float4 v1 = ((const float4*)g_v)[(size_t)kj1 * 32 + lane];
        float d0 = q0.x * kv.x + q0.y * kv.y + q0.z * kv.z + q0.w * kv.w;
        float d1 = q1.x * kv.x + q1.y * kv.y + q1.z * kv.z + q1.w * kv.w;
        d0 += __shfl_xor_sync(0xffffffffu, d0, 1);
        d1 += __shfl_xor_sync(0xffffffffu, d1, 1);
        d0 += __shfl_xor_sync(0xffffffffu, d0, 2);
        d1 += __shfl_xor_sync(0xffffffffu, d1, 2);
        float s0 = d0 > 0.f ? d0 : 0.2f * d0;
        float s1 = d1 > 0.f ? d1 : 0.2f * d1;
        float a0 = expf(s0);
        float a1 = expf(s1);
        denom += a0 + a1;
        acc.x += a0 * v0.x + a1 * v1.x;
        acc.y += a0 * v0.y + a1 * v1.y;
        acc.z += a0 * v0.z + a1 * v1.z;
        acc.w += a0 * v0.w + a1 * v1.w;
    }
    if (p < end) {
        int kj = __ldg(&g_perm[p]);
        float4 qv = ((const float4*)g_q)[(size_t)kj * 32 + lane];
        float4 vv = ((const float4*)g_v)[(size_t)kj * 32 + lane];
        float d = qv.x * kv.x + qv.y * kv.y + qv.z * kv.z + qv.w * kv.w;
        d += __shfl_xor_sync(0xffffffffu, d, 1);
        d += __shfl_xor_sync(0xffffffffu, d, 2);
        float s = d > 0.f ? d : 0.2f * d;
        float a = expf(s);
        denom += a;
        acc.x += a * vv.x; acc.y += a * vv.y;
        acc.z += a * vv.z; acc.w += a * vv.w;
    }

    float inv = (end > start) ? 1.f / denom : 0.f;
    float4 o = make_float4(acc.x * inv, acc.y * inv, acc.z * inv, acc.w * inv);
    ((float4*)g_agg)[(size_t)n * 32 + lane] = o;
}

// ---------------- launch ----------------
extern "C" void kernel_launch(void* const* d_in, const int* in_sizes, int n_in,
                              void* d_out, int out_size) {
    const float* feats = (const float*)d_in[0];
    const void*  idx_kj = d_in[1];
    const void*  idx_ji = d_in[2];
    const float* Wv = (const float*)d_in[3];
    const float* Wq = (const float*)d_in[4];
    const float* Wk = (const float*)d_in[5];
    const float* W1 = (const float*)d_in[6];
    const float* b1 = (const float*)d_in[7];
    const float* W2 = (const float*)d_in[8];
    const float* b2 = (const float*)d_in[9];
    float* out = (float*)d_out;

    int nrows = in_sizes[0] / HID;
    int m     = in_sizes[1];

    float *q_p, *k_p, *v_p, *agg_p;
    cudaGetSymbolAddress((void**)&q_p,   g_q);
    cudaGetSymbolAddress((void**)&k_p,   g_k);
    cudaGetSymbolAddress((void**)&v_p,   g_v);
    cudaGetSymbolAddress((void**)&agg_p, g_agg);

    cudaFuncSetAttribute(gemm_qkv, cudaFuncAttributeMaxDynamicSharedMemorySize,
                         GEMM_SMEM);
    cudaFuncSetAttribute(gemm_mlp, cudaFuncAttributeMaxDynamicSharedMemorySize,
                         GEMM_SMEM);

    // side stream + events for overlapping the sort chain with gemm_qkv
    static cudaStream_t s_side = nullptr;
    static cudaEvent_t  ev_fork = nullptr, ev_join = nullptr;
    if (!s_side) {
        cudaStreamCreateWithFlags(&s_side, cudaStreamNonBlocking);
        cudaEventCreateWithFlags(&ev_fork, cudaEventDisableTiming);
        cudaEventCreateWithFlags(&ev_join, cudaEventDisableTiming);
    }

    // fork: sort triplets by destination on the side stream
    cudaEventRecord(ev_fork, 0);
    cudaStreamWaitEvent(s_side, ev_fork, 0);
    detect_kernel<<<1, 256, 0, s_side>>>((const unsigned int*)idx_kj, m);
    zero_hist<<<256, 256, 0, s_side>>>();
    hist_kernel<<<1024, 256, 0, s_side>>>(idx_ji, m);
    scan1_kernel<<<NBLK, 1024, 0, s_side>>>();
    scan2_kernel<<<1, 1, 0, s_side>>>();
    scan3_kernel<<<256, 256, 0, s_side>>>();
    scatter_kernel<<<1024, 256, 0, s_side>>>(idx_ji, idx_kj, m);
    cudaEventRecord(ev_join, s_side);

    // main stream: QKV projections (independent of the sort)
    int gblocks = (nrows + 63) / 64;
    gemm_qkv<<<gblocks, 256, GEMM_SMEM>>>(feats, Wq, Wk, Wv, q_p, k_p, v_p, nrows);

    // join, then attention + fused MLP
    cudaStreamWaitEvent(0, ev_join, 0);
    int ablocks = (NROWS * 32 + 255) / 256;
    att_agg_kernel<<<ablocks, 256>>>();

    gemm_mlp<<<gblocks, 256, GEMM_SMEM>>>(agg_p, W1, b1, W2, b2, v_p, out, nrows);
}